// round 1
// baseline (speedup 1.0000x reference)
#include <cuda_runtime.h>
#include <math.h>

// Problem constants (from reference): x is [2048, 512, 7, 7] fp32.
#define NCH    512
#define HW     49
#define SLAB   (NCH * HW)          // 25088 floats per sample
#define SLAB4  (SLAB / 4)          // 6272 float4 per sample
#define NTHREADS 512
#define EPS    1e-5f

// Dynamic smem layout: [SLAB floats slab][NCH floats gate][64 floats reduction]
#define SMEM_FLOATS (SLAB + NCH + 64)
#define SMEM_BYTES  (SMEM_FLOATS * sizeof(float))

__global__ __launch_bounds__(NTHREADS, 2)
void ModelNew_25056839205377_kernel(const float* __restrict__ x,
                                    float* __restrict__ out)
{
    extern __shared__ float sm[];
    float* s    = sm;            // slab [SLAB]
    float* gate = sm + SLAB;     // [NCH]
    float* red  = gate + NCH;    // [64]: 16 partial sums, 16 partial sumsq, 2 bcast

    const int tid = threadIdx.x;
    const size_t base = (size_t)blockIdx.x * SLAB;

    // ---- Phase 1: coalesced load of the whole sample slab into SMEM ----
    const float4* __restrict__ xin = (const float4*)(x + base);
    float4* s4 = (float4*)s;
    #pragma unroll
    for (int i = tid; i < SLAB4; i += NTHREADS)
        s4[i] = xin[i];
    __syncthreads();

    // ---- Phase 2: per-channel spatial mean (thread c handles channel c) ----
    // Addresses c*49 + k across a warp: stride 49 words, gcd(49,32)=1 -> conflict-free.
    const float* row = s + tid * HW;
    float a0 = 0.f, a1 = 0.f, a2 = 0.f, a3 = 0.f;
    #pragma unroll
    for (int k = 0; k < 48; k += 4) {
        a0 += row[k + 0];
        a1 += row[k + 1];
        a2 += row[k + 2];
        a3 += row[k + 3];
    }
    float y = ((a0 + a1) + (a2 + a3) + row[48]) * (1.0f / HW);

    // ---- Phase 3: block reduction of sum(y) and sum(y^2) over 512 channels ----
    float ys = y, y2 = y * y;
    #pragma unroll
    for (int o = 16; o > 0; o >>= 1) {
        ys += __shfl_xor_sync(0xffffffffu, ys, o);
        y2 += __shfl_xor_sync(0xffffffffu, y2, o);
    }
    const int warp = tid >> 5, lane = tid & 31;
    if (lane == 0) { red[warp] = ys; red[16 + warp] = y2; }
    __syncthreads();
    if (warp == 0) {
        float s1 = (lane < 16) ? red[lane]      : 0.f;
        float s2 = (lane < 16) ? red[16 + lane] : 0.f;
        #pragma unroll
        for (int o = 8; o > 0; o >>= 1) {
            s1 += __shfl_xor_sync(0xffffffffu, s1, o);
            s2 += __shfl_xor_sync(0xffffffffu, s2, o);
        }
        if (lane == 0) {
            float m   = s1 * (1.0f / NCH);
            float mx2 = s2 * (1.0f / NCH);
            float var = fmaxf(mx2 - m * m, 0.0f);
            red[32] = m;
            red[33] = rsqrtf(var + EPS);
        }
    }
    __syncthreads();

    // ---- Phase 4: gate[c] = exp(-0.5 * C_PARAM * z^2) = exp(-z^2)  (C_PARAM=2)
    const float m   = red[32];
    const float inv = red[33];
    const float z   = (y - m) * inv;
    gate[tid] = __expf(-z * z);
    __syncthreads();

    // ---- Phase 5: multiply slab by per-channel gate, coalesced float4 store ----
    float4* __restrict__ o4 = (float4*)(out + base);
    #pragma unroll
    for (int i = tid; i < SLAB4; i += NTHREADS) {
        float4 v = s4[i];
        const int e = i * 4;
        v.x *= gate[(e + 0) / HW];
        v.y *= gate[(e + 1) / HW];
        v.z *= gate[(e + 2) / HW];
        v.w *= gate[(e + 3) / HW];
        o4[i] = v;
    }
}

extern "C" void kernel_launch(void* const* d_in, const int* in_sizes, int n_in,
                              void* d_out, int out_size)
{
    const float* x = (const float*)d_in[0];
    float* out = (float*)d_out;
    const int nblocks = in_sizes[0] / SLAB;   // 2048 samples

    // Opt-in to >48KB dynamic shared memory (idempotent; not an allocation).
    cudaFuncSetAttribute(ModelNew_25056839205377_kernel,
                         cudaFuncAttributeMaxDynamicSharedMemorySize,
                         (int)SMEM_BYTES);

    ModelNew_25056839205377_kernel<<<nblocks, NTHREADS, SMEM_BYTES>>>(x, out);
}

// round 3
// speedup vs baseline: 1.0679x; 1.0679x over previous
#include <cuda_runtime.h>
#include <math.h>

// x: [2048, 512, 7, 7] fp32.
#define NCH      512
#define HW       49
#define SLAB     (NCH * HW)      // 25088 floats / sample
#define SLAB4    (SLAB / 4)      // 6272 float4 / sample
#define NTHREADS 512
#define NWARPS   (NTHREADS / 32) // 16
#define CH_PER_W (NCH / NWARPS)  // 32 channels per warp
#define EPS      1e-5f

__global__ __launch_bounds__(NTHREADS, 4)
void ModelNew_25056839205377_kernel(const float* __restrict__ x,
                                    float* __restrict__ out)
{
    __shared__ float ch[NCH + 1];   // y[c], later gate[c]; +1 slack for c+1 read
    __shared__ float red[34];       // 16 sums, 16 sumsqs, 2 bcast

    const int tid  = threadIdx.x;
    const int warp = tid >> 5;
    const int lane = tid & 31;
    const size_t base = (size_t)blockIdx.x * SLAB;
    const float* __restrict__ xp = x + base;

    // ---- Phase 1: y[c] = spatial mean. Each warp owns 32 channels. ----
    // 49 contiguous floats per channel: lanes 0..31 + predicated lanes 0..16.
    #pragma unroll 4
    for (int k = 0; k < CH_PER_W; ++k) {
        const int c = warp * CH_PER_W + k;           // covers 0..511
        const float* p = xp + c * HW;
        float s = p[lane] + ((lane < HW - 32) ? p[32 + lane] : 0.0f);
        #pragma unroll
        for (int o = 16; o > 0; o >>= 1)
            s += __shfl_xor_sync(0xffffffffu, s, o);
        if (lane == 0) ch[c] = s * (1.0f / HW);
    }
    __syncthreads();

    // ---- Phase 2: stats over 512 channels (thread c owns channel c) ----
    const float y = ch[tid];
    float ys = y, y2 = y * y;
    #pragma unroll
    for (int o = 16; o > 0; o >>= 1) {
        ys += __shfl_xor_sync(0xffffffffu, ys, o);
        y2 += __shfl_xor_sync(0xffffffffu, y2, o);
    }
    if (lane == 0) { red[warp] = ys; red[16 + warp] = y2; }
    __syncthreads();
    if (warp == 0) {
        float s1 = (lane < 16) ? red[lane]      : 0.0f;
        float s2 = (lane < 16) ? red[16 + lane] : 0.0f;
        #pragma unroll
        for (int o = 8; o > 0; o >>= 1) {
            s1 += __shfl_xor_sync(0xffffffffu, s1, o);
            s2 += __shfl_xor_sync(0xffffffffu, s2, o);
        }
        if (lane == 0) {
            const float m   = s1 * (1.0f / NCH);
            const float mx2 = s2 * (1.0f / NCH);
            const float var = fmaxf(mx2 - m * m, 0.0f);
            red[32] = m;
            red[33] = rsqrtf(var + EPS);
        }
    }
    __syncthreads();

    // ---- Phase 3: gate[c] = exp(-z^2)  (C_PARAM=2 -> -0.5*2*z^2 = -z^2) ----
    {
        const float m   = red[32];
        const float inv = red[33];
        const float z   = (y - m) * inv;
        ch[tid] = __expf(-z * z);
    }
    if (tid == 0) ch[NCH] = 0.0f;   // slack slot for predicated c+1 reads
    __syncthreads();

    // ---- Phase 4: re-read x (L2-resident), multiply by gate, store ----
    const float4* __restrict__ x4 = (const float4*)xp;
    float4* __restrict__ o4 = (float4*)(out + base);
    #pragma unroll
    for (int i = tid; i < SLAB4; i += NTHREADS) {
        float4 v = x4[i];
        const int e = i * 4;
        const int c = e / HW;                // constant div -> mul+shift
        const int r = e - c * HW;            // 0..48
        const float g0 = ch[c];
        const float gn = ch[c + 1];
        v.x *= g0;                           // r     <= 48 always in channel c
        v.y *= (r < 48) ? g0 : gn;           // crosses when r+1 == 49
        v.z *= (r < 47) ? g0 : gn;           // crosses when r+2 >= 49
        v.w *= (r < 46) ? g0 : gn;           // crosses when r+3 >= 49
        o4[i] = v;
    }
}

extern "C" void kernel_launch(void* const* d_in, const int* in_sizes, int n_in,
                              void* d_out, int out_size)
{
    const float* x = (const float*)d_in[0];
    float* out = (float*)d_out;
    const int nblocks = in_sizes[0] / SLAB;   // 2048 samples
    ModelNew_25056839205377_kernel<<<nblocks, NTHREADS>>>(x, out);
}